// round 7
// baseline (speedup 1.0000x reference)
#include <cuda_runtime.h>
#include <cstdint>

// ---------------------------------------------------------------------------
// BinaryNet forward, fully bitwise.
//   conv1: 1->4ch, 15x15 -> 7x7, stride2, 9 terms (odd -> pure binary out)
//   conv2: 4->8ch, 7x7 -> 3x3, stride2, 36 terms (ternary out: v,m bits)
//   conv3: 8->16ch, 3x3 -> 1x1, 72 terms (ternary)
//   fc1:   16->8 (ternary), fc2: 8->1 (integer -> float)
// ---------------------------------------------------------------------------

__device__ uint32_t           g_w1p[4];
__device__ unsigned long long g_w2p[8];     // bit ((dr*3+dc)*4 + ic)
__device__ unsigned long long g_w3p[32];    // [o*2+half], bit (ic*9 + pix)
__device__ uint32_t           g_wfc1p[8];
__device__ uint32_t           g_wfc2p[1];

__global__ void pack_weights_kernel(const float* __restrict__ w1,
                                    const float* __restrict__ w2,
                                    const float* __restrict__ w3,
                                    const float* __restrict__ wfc1,
                                    const float* __restrict__ wfc2) {
    int t = threadIdx.x;
    if (t < 4) {
        uint32_t p = 0;
        for (int k = 0; k < 9; k++) p |= (uint32_t)(w1[t * 9 + k] > 0.0f) << k;
        g_w1p[t] = p;
    }
    if (t < 8) {
        unsigned long long p = 0;
        for (int ic = 0; ic < 4; ic++)
            for (int k = 0; k < 9; k++)
                p |= (unsigned long long)(w2[(t * 4 + ic) * 9 + k] > 0.0f)
                     << (k * 4 + ic);   // matches nibble-packed a1 layout
        g_w2p[t] = p;
        uint32_t q = 0;
        for (int j = 0; j < 16; j++) q |= (uint32_t)(wfc1[t * 16 + j] > 0.0f) << j;
        g_wfc1p[t] = q;
    }
    if (t < 16) {
        unsigned long long lo = 0, hi = 0;
        for (int ic = 0; ic < 4; ic++)
            for (int k = 0; k < 9; k++) {
                lo |= (unsigned long long)(w3[(t * 8 + ic) * 9 + k]     > 0.0f) << (ic * 9 + k);
                hi |= (unsigned long long)(w3[(t * 8 + ic + 4) * 9 + k] > 0.0f) << (ic * 9 + k);
            }
        g_w3p[t * 2]     = lo;
        g_w3p[t * 2 + 1] = hi;
    }
    if (t == 0) {
        uint32_t p = 0;
        for (int j = 0; j < 8; j++) p |= (uint32_t)(wfc2[j] > 0.0f) << j;
        g_wfc2p[0] = p;
    }
}

__global__ __launch_bounds__(256) void bnn_kernel(const float* __restrict__ x,
                                                  float* __restrict__ out,
                                                  int B) {
    // 256 images/block. Bitstream: 256*225 bits = 1800 words (+1 pad for funnel).
    __shared__ uint32_t           sbits[1801];
    __shared__ uint8_t            s_lut1[512];   // 9-bit patch -> 4 conv1 sign bits
    __shared__ unsigned long long s_w2p[8];
    __shared__ unsigned long long s_w3p[32];
    __shared__ uint32_t           s_wfc1p[8];
    __shared__ uint32_t           s_wfc2p;

    const int tid  = threadIdx.x;
    const int wrp  = tid >> 5;
    const int lane = tid & 31;

    // --- stage weights into shared ---
    if (tid < 8)  { s_w2p[tid] = g_w2p[tid]; s_wfc1p[tid] = g_wfc1p[tid]; }
    if (tid < 32) s_w3p[tid] = g_w3p[tid];
    if (tid == 0) s_wfc2p = g_wfc2p[0];

    // --- build conv1 LUT: entry e -> nibble of (popc(e^w1[o]) <= 4) bits ---
    {
        uint32_t wa = g_w1p[0], wb = g_w1p[1], wc = g_w1p[2], wd = g_w1p[3];
        #pragma unroll
        for (int e = tid; e < 512; e += 256) {
            uint32_t nib =  (uint32_t)(__popc((uint32_t)e ^ wa) <= 4)
                         | ((uint32_t)(__popc((uint32_t)e ^ wb) <= 4) << 1)
                         | ((uint32_t)(__popc((uint32_t)e ^ wc) <= 4) << 2)
                         | ((uint32_t)(__popc((uint32_t)e ^ wd) <= 4) << 3);
            s_lut1[e] = (uint8_t)nib;
        }
    }

    // --- coalesced load + warp-ballot binarization into shared bitstream ---
    const int blockBase = blockIdx.x * (256 * 225);
    const int total     = B * 225;
    #pragma unroll 9
    for (int k = 0; k < 225; k++) {
        int j   = wrp * 225 + k;                 // word index in block bitstream
        int idx = blockBase + (j << 5) + lane;   // 32 consecutive floats per LDG
        float v = (idx < total) ? __ldg(x + idx) : 0.0f;
        uint32_t b = __ballot_sync(0xFFFFFFFFu, v > 0.0f);
        if (lane == 0) sbits[j] = b;
    }
    __syncthreads();

    const int img = blockIdx.x * 256 + tid;
    if (img >= B) return;

    // --- extract 15 rows of 15 bits for this image ---
    uint32_t rows[15];
    const int base = tid * 225;
    #pragma unroll
    for (int r = 0; r < 15; r++) {
        int off = base + r * 15;
        uint32_t lo = sbits[off >> 5];
        uint32_t hi = sbits[(off >> 5) + 1];
        rows[r] = __funnelshift_r(lo, hi, off & 31) & 0x7FFFu;
    }

    // --- conv1: 7x7 output, 4 channels, nibble-packed per row ---
    uint32_t a1row[7];   // row r: 7 nibbles, nibble oc bit ic = sign of ch ic at (r,oc)
    #pragma unroll
    for (int orow = 0; orow < 7; orow++) {
        uint32_t r0 = rows[2 * orow], r1 = rows[2 * orow + 1], r2 = rows[2 * orow + 2];
        uint32_t acc = 0;
        #pragma unroll
        for (int oc = 0; oc < 7; oc++) {
            uint32_t patch = ((r0 >> (2 * oc)) & 7u)
                           | (((r1 >> (2 * oc)) & 7u) << 3)
                           | (((r2 >> (2 * oc)) & 7u) << 6);
            acc |= (uint32_t)s_lut1[patch] << (4 * oc);
        }
        a1row[orow] = acc;
    }

    // --- conv2: 3x3 output, 8 channels, ternary (v,m). 36-bit patch vs w2 ---
    unsigned long long v2lo = 0, v2hi = 0, m2lo = 0, m2hi = 0;
    #pragma unroll
    for (int R = 0; R < 3; R++) {
        uint32_t q0 = a1row[2 * R], q1 = a1row[2 * R + 1], q2 = a1row[2 * R + 2];
        #pragma unroll
        for (int C = 0; C < 3; C++) {
            unsigned long long patch =
                  (unsigned long long)((q0 >> (8 * C)) & 0xFFFu)
                | ((unsigned long long)((q1 >> (8 * C)) & 0xFFFu) << 12)
                | ((unsigned long long)((q2 >> (8 * C)) & 0xFFFu) << 24);
            const int pix = R * 3 + C;
            #pragma unroll
            for (int o = 0; o < 8; o++) {
                int d = __popcll(patch ^ s_w2p[o]);      // sum = 36 - 2d
                unsigned long long vb = (unsigned long long)(d < 18);
                unsigned long long mb = (unsigned long long)(d != 18);
                if (o < 4) {
                    v2lo |= vb << (o * 9 + pix);
                    m2lo |= mb << (o * 9 + pix);
                } else {
                    v2hi |= vb << ((o - 4) * 9 + pix);
                    m2hi |= mb << ((o - 4) * 9 + pix);
                }
            }
        }
    }

    // --- conv3: 1x1 output, 16 channels, ternary-in ternary-out ---
    const int mc2 = __popcll(m2lo) + __popcll(m2hi);
    uint32_t v3 = 0, m3 = 0;
    #pragma unroll
    for (int o = 0; o < 16; o++) {
        int d = __popcll(m2lo & (v2lo ^ s_w3p[2 * o]))
              + __popcll(m2hi & (v2hi ^ s_w3p[2 * o + 1]));
        int s = mc2 - 2 * d;
        v3 |= (uint32_t)(s > 0)  << o;
        m3 |= (uint32_t)(s != 0) << o;
    }

    // --- fc1: 16 -> 8, ternary ---
    const int mc3 = __popc(m3);
    uint32_t v4 = 0, m4 = 0;
    #pragma unroll
    for (int o = 0; o < 8; o++) {
        int d = __popc(m3 & (v3 ^ s_wfc1p[o]));
        int s = mc3 - 2 * d;
        v4 |= (uint32_t)(s > 0)  << o;
        m4 |= (uint32_t)(s != 0) << o;
    }

    // --- fc2: 8 -> 1, integer output ---
    int d5 = __popc(m4 & (v4 ^ s_wfc2p));
    out[img] = (float)(__popc(m4) - 2 * d5);
}

extern "C" void kernel_launch(void* const* d_in, const int* in_sizes, int n_in,
                              void* d_out, int out_size) {
    const float* x    = (const float*)d_in[0];
    const float* w1   = (const float*)d_in[1];
    const float* w2   = (const float*)d_in[2];
    const float* w3   = (const float*)d_in[3];
    const float* wfc1 = (const float*)d_in[4];
    const float* wfc2 = (const float*)d_in[5];
    float* out = (float*)d_out;

    int B = in_sizes[0] / 225;          // x is [B,1,15,15]
    pack_weights_kernel<<<1, 32>>>(w1, w2, w3, wfc1, wfc2);
    int blocks = (B + 255) / 256;
    bnn_kernel<<<blocks, 256>>>(x, out, B);
}